// round 6
// baseline (speedup 1.0000x reference)
#include <cuda_runtime.h>
#include <cstdint>

// Problem constants
#define BB 4
#define SS 2048
#define DD 1024
#define HH 16
#define HD 64
#define MM (BB*SS)   // 8192

// Scratch
__device__ float g_q[BB*HH*SS*HD];
__device__ float g_k[BB*HH*SS*HD];
__device__ float g_v[BB*HH*SS*HD];
__device__ float g_ctx[BB*SS*DD];
__device__ float g_xr[MM*DD];        // tf32-rounded x
__device__ float g_wr[4*DD*DD];      // tf32-rounded Wq|Wk|Wv|Wo

// ---------------------------------------------------------------------------
// Helpers (plain-sm_103-legal PTX only: mma.sync sm_80+, ldmatrix sm_75+)
// ---------------------------------------------------------------------------
__device__ __forceinline__ uint32_t smem_u32(const void* p) {
    uint32_t a;
    asm("{ .reg .u64 t; cvta.to.shared.u64 t, %1; cvt.u32.u64 %0, t; }"
        : "=r"(a) : "l"(p));
    return a;
}

__device__ __forceinline__ uint32_t cvt_tf32(float f) {
    uint32_t o;
    asm("cvt.rn.tf32.f32 %0, %1;" : "=r"(o) : "f"(f));
    return o;
}

__device__ __forceinline__ void mma_tf32(float* d, const uint32_t* a, const uint32_t* b) {
    asm volatile("mma.sync.aligned.m16n8k8.row.col.f32.tf32.tf32.f32 "
        "{%0,%1,%2,%3}, {%4,%5,%6,%7}, {%8,%9}, {%0,%1,%2,%3};"
        : "+f"(d[0]), "+f"(d[1]), "+f"(d[2]), "+f"(d[3])
        : "r"(a[0]), "r"(a[1]), "r"(a[2]), "r"(a[3]), "r"(b[0]), "r"(b[1]));
}

// 4x (8x8 b16) matrices; with tf32 data: one m16k8 A-frag or two n8k8 B-frags.
#define LDSM_X4(r, addr) \
    asm volatile("ldmatrix.sync.aligned.m8n8.x4.shared.b16 {%0,%1,%2,%3}, [%4];" \
        : "=r"((r)[0]), "=r"((r)[1]), "=r"((r)[2]), "=r"((r)[3]) : "r"(addr))

#define CP_ASYNC16(dst, src) \
    asm volatile("cp.async.cg.shared.global [%0], [%1], 16;" :: "r"(dst), "l"(src) : "memory")
#define CP_COMMIT() asm volatile("cp.async.commit_group;" ::: "memory")
#define CP_WAIT0()  asm volatile("cp.async.wait_group 0;" ::: "memory")
#define CP_WAIT1()  asm volatile("cp.async.wait_group 1;" ::: "memory")

// ---------------------------------------------------------------------------
// Prep: RN-round x and the 4 weight matrices to tf32 (one pass, once).
// ---------------------------------------------------------------------------
#define XR_F4 (MM*DD/4)
#define WR_F4 (DD*DD/4)

__global__ __launch_bounds__(256)
void round_prep(const float* __restrict__ x,
                const float* __restrict__ Wq, const float* __restrict__ Wk,
                const float* __restrict__ Wv, const float* __restrict__ Wo,
                float* __restrict__ xr, float* __restrict__ wr)
{
    const int idx = blockIdx.x * blockDim.x + threadIdx.x;
    const float4* src;
    float4* dst;
    int off;
    if (idx < XR_F4) {
        src = (const float4*)x; dst = (float4*)xr; off = idx;
    } else {
        const int t = idx - XR_F4;
        const int sel = t >> 18;
        off = t & (WR_F4 - 1);
        const float* ws = (sel == 0) ? Wq : (sel == 1) ? Wk : (sel == 2) ? Wv : Wo;
        src = (const float4*)ws;
        dst = (float4*)(wr + (size_t)sel * DD * DD);
    }
    float4 v = src[off];
    float4 o;
    o.x = __uint_as_float(cvt_tf32(v.x));
    o.y = __uint_as_float(cvt_tf32(v.y));
    o.z = __uint_as_float(cvt_tf32(v.z));
    o.w = __uint_as_float(cvt_tf32(v.w));
    dst[off] = o;
}

// ---------------------------------------------------------------------------
// tf32 warp-MMA GEMM body, ldmatrix fragment loads.
// ---------------------------------------------------------------------------
#define GSTAGE (128*36)

template <bool QKV>
__device__ __forceinline__
void gemm_body(float* smemf,
               const float* __restrict__ A, const float* __restrict__ W,
               const float* __restrict__ bias, float* __restrict__ C)
{
    float* As = smemf;
    float* Ws = smemf + 3*GSTAGE;
    const uint32_t As_u = smem_u32(As);
    const uint32_t Ws_u = smem_u32(Ws);

    const int tid  = threadIdx.x;
    const int lane = tid & 31, wid = tid >> 5;
    const int q = lane & 3, g = lane >> 2;
    const int mbase = (wid >> 2) * 64;
    const int nbase = (wid & 3) * 32;
    const int rowBase = blockIdx.y * 128;
    const int colBase = blockIdx.x * 128;

    // ldmatrix lane addressing (floats)
    const int laRow = lane & 15;                         // A: row within m16
    const int laCol = (lane & 16) ? 4 : 0;               // A: k half
    const int lbRow = (lane & 7) + ((lane & 16) ? 8 : 0);// B: row within n16
    const int lbCol = (lane & 8) ? 4 : 0;                // B: k half
    // byte offsets within a stage
    uint32_t aoff[4], boff[2];
    #pragma unroll
    for (int mt = 0; mt < 4; mt++)
        aoff[mt] = (uint32_t)(((mbase + mt*16 + laRow)*36 + laCol) * 4);
    #pragma unroll
    for (int p = 0; p < 2; p++)
        boff[p] = (uint32_t)(((nbase + p*16 + lbRow)*36 + lbCol) * 4);

    int lr[4], lg[4];
    #pragma unroll
    for (int i = 0; i < 4; i++) { int c = tid + i*256; lr[i] = c >> 3; lg[i] = c & 7; }

    float d[4][4][4];
    #pragma unroll
    for (int mt = 0; mt < 4; mt++)
        #pragma unroll
        for (int nt = 0; nt < 4; nt++)
            #pragma unroll
            for (int e = 0; e < 4; e++) d[mt][nt][e] = 0.f;

    auto issue = [&](int kt) {
        const int slot = kt % 3;
        const uint32_t adst = As_u + (uint32_t)(slot * GSTAGE) * 4u;
        const uint32_t wdst = Ws_u + (uint32_t)(slot * GSTAGE) * 4u;
        #pragma unroll
        for (int i = 0; i < 4; i++) {
            const uint32_t off = (uint32_t)(lr[i]*36 + lg[i]*4) * 4u;
            CP_ASYNC16(adst + off, A + (size_t)(rowBase + lr[i])*DD + kt*32 + lg[i]*4);
            CP_ASYNC16(wdst + off, W + (size_t)(colBase + lr[i])*DD + kt*32 + lg[i]*4);
        }
        CP_COMMIT();
    };

    issue(0);
    issue(1);

    for (int kt = 0; kt < 32; kt++) {
        if (kt == 31) CP_WAIT0(); else CP_WAIT1();
        __syncthreads();
        if (kt + 2 < 32) issue(kt + 2);

        const uint32_t A_su = As_u + (uint32_t)((kt % 3) * GSTAGE) * 4u;
        const uint32_t W_su = Ws_u + (uint32_t)((kt % 3) * GSTAGE) * 4u;
        #pragma unroll
        for (int ks = 0; ks < 4; ks++) {
            uint32_t af[4][4], bf[2][4];   // bf[p] = two n8 tiles' {b0,b1}
            #pragma unroll
            for (int mt = 0; mt < 4; mt++)
                LDSM_X4(af[mt], A_su + aoff[mt] + (uint32_t)(ks*32));
            #pragma unroll
            for (int p = 0; p < 2; p++)
                LDSM_X4(bf[p], W_su + boff[p] + (uint32_t)(ks*32));
            #pragma unroll
            for (int mt = 0; mt < 4; mt++) {
                #pragma unroll
                for (int p = 0; p < 2; p++) {
                    mma_tf32(d[mt][2*p + 0], af[mt], &bf[p][0]);
                    mma_tf32(d[mt][2*p + 1], af[mt], &bf[p][2]);
                }
            }
        }
    }

    #pragma unroll
    for (int nt = 0; nt < 4; nt++) {
        const int n0 = colBase + nbase + nt*8 + 2*q;
        const float b0 = bias[n0], b1 = bias[n0 + 1];
        #pragma unroll
        for (int mt = 0; mt < 4; mt++) {
            const int m0 = rowBase + mbase + mt*16 + g;
            #pragma unroll
            for (int half = 0; half < 2; half++) {
                const int m = m0 + half*8;
                float2 o;
                if (QKV) {
                    o.x = __uint_as_float(cvt_tf32(d[mt][nt][half*2 + 0] + b0));
                    o.y = __uint_as_float(cvt_tf32(d[mt][nt][half*2 + 1] + b1));
                    const int b  = m >> 11;
                    const int s  = m & (SS - 1);
                    const int h  = n0 >> 6;
                    const int hd = n0 & 63;
                    *(float2*)(C + (((size_t)(b*HH + h)*SS + s)*HD + hd)) = o;
                } else {
                    o.x = d[mt][nt][half*2 + 0] + b0;
                    o.y = d[mt][nt][half*2 + 1] + b1;
                    *(float2*)(C + (size_t)m*DD + n0) = o;
                }
            }
        }
    }
}

__global__ __launch_bounds__(256, 2)
void gemm_qkv(const float* __restrict__ A, const float* __restrict__ Wr,
              const float* __restrict__ b0, const float* __restrict__ b1,
              const float* __restrict__ b2,
              float* __restrict__ C0, float* __restrict__ C1, float* __restrict__ C2)
{
    extern __shared__ float smemf[];
    const int z = blockIdx.z;
    const float* W = Wr + (size_t)z * DD * DD;
    const float* b = (z == 0) ? b0 : (z == 1) ? b1 : b2;
    float*       C = (z == 0) ? C0 : (z == 1) ? C1 : C2;
    gemm_body<true>(smemf, A, W, b, C);
}

__global__ __launch_bounds__(256, 2)
void gemm_out(const float* __restrict__ A, const float* __restrict__ W,
              const float* __restrict__ bias, float* __restrict__ C)
{
    extern __shared__ float smemf[];
    gemm_body<false>(smemf, A, W, bias, C);
}

// ---------------------------------------------------------------------------
// tf32 warp-MMA flash-attention, v4: K b-fragments via ldmatrix.
// ---------------------------------------------------------------------------
#define KSTR 68
#define VSTR 72
#define QSTR 72
#define KBUF (64*KSTR)
#define VBUF (64*VSTR)

__global__ __launch_bounds__(256, 2)
void attn_mma(const float* __restrict__ Q, const float* __restrict__ K,
              const float* __restrict__ V, float* __restrict__ ctx)
{
    extern __shared__ float sf[];
    float* Qs = sf;                    // [128][72] permuted-pair layout
    float* Ks = sf + 128*QSTR;         // [2][64][68]
    float* Vs = Ks + 2*KBUF;           // [2][64][72]
    const uint32_t Ks_u = smem_u32(Ks);
    const uint32_t Vs_u = smem_u32(Vs);

    const int tid  = threadIdx.x;
    const int lane = tid & 31, wid = tid >> 5;
    const int q = lane & 3, g = lane >> 2;
    const int bh = blockIdx.y, qt = blockIdx.x;

    const float* Qb = Q + (size_t)bh*SS*HD + (size_t)qt*128*HD;
    const float* Kb = K + (size_t)bh*SS*HD;
    const float* Vb = V + (size_t)bh*SS*HD;

    // ldmatrix lane addressing for K (B-side, two n8 tiles per x4)
    const int lbRow = (lane & 7) + ((lane & 16) ? 8 : 0);
    const int lbCol = (lane & 8) ? 4 : 0;
    const uint32_t klane = (uint32_t)((lbRow*KSTR + lbCol) * 4);

    // Q pre-rounded; *0.125 exact. Store pair-permuted.
    #pragma unroll
    for (int i = 0; i < 8; i++) {
        const int c = tid + i*256;
        const int r = c >> 4, d0 = (c & 15) * 4;
        float4 v = *(const float4*)(Qb + r*HD + d0);
        const int base = (d0 & ~7) + ((d0 & 4) ? 1 : 0);
        Qs[r*QSTR + base + 0] = v.x * 0.125f;
        Qs[r*QSTR + base + 2] = v.y * 0.125f;
        Qs[r*QSTR + base + 4] = v.z * 0.125f;
        Qs[r*QSTR + base + 6] = v.w * 0.125f;
    }

    auto issue_kv = [&](int kt) {
        const int buf = kt & 1;
        #pragma unroll
        for (int i = 0; i < 4; i++) {
            const int c = tid + i*256;
            const int r = c >> 4, d0 = (c & 15) * 4;
            CP_ASYNC16(Ks_u + (uint32_t)(buf*KBUF + r*KSTR + d0)*4u,
                       Kb + (size_t)(kt*64 + r)*HD + d0);
            CP_ASYNC16(Vs_u + (uint32_t)(buf*VBUF + r*VSTR + d0)*4u,
                       Vb + (size_t)(kt*64 + r)*HD + d0);
        }
        CP_COMMIT();
    };

    const int r0 = wid*16 + g;

    float m0 = -1e30f, m1 = -1e30f, l0 = 0.f, l1 = 0.f;
    float o[8][4];
    #pragma unroll
    for (int nt = 0; nt < 8; nt++)
        #pragma unroll
        for (int e = 0; e < 4; e++) o[nt][e] = 0.f;

    issue_kv(0);

    const int srcA = (lane & ~3) | (q >> 1);
    const int srcB = srcA + 2;
    const bool hi  = (q & 1) != 0;

    for (int kt = 0; kt < SS/64; kt++) {
        CP_WAIT0();
        __syncthreads();
        if (kt + 1 < SS/64) issue_kv(kt + 1);

        const uint32_t Kc_u = Ks_u + (uint32_t)((kt & 1) * KBUF) * 4u;
        const float* Vc = Vs + (kt & 1) * VBUF;

        // --- QK^T: a-frag from Qs (LDS.64 pair trick), b-frag via ldmatrix ---
        float s[8][4];
        #pragma unroll
        for (int nt = 0; nt < 8; nt++)
            #pragma unroll
            for (int e = 0; e < 4; e++) s[nt][e] = 0.f;

        #pragma unroll
        for (int ks = 0; ks < 8; ks++) {
            uint32_t a[4];
            float2 qa = *(const float2*)(Qs + r0*QSTR     + ks*8 + 2*q);
            float2 qb = *(const float2*)(Qs + (r0+8)*QSTR + ks*8 + 2*q);
            a[0] = __float_as_uint(qa.x);
            a[1] = __float_as_uint(qb.x);
            a[2] = __float_as_uint(qa.y);
            a[3] = __float_as_uint(qb.y);
            #pragma unroll
            for (int p = 0; p < 4; p++) {
                uint32_t bk[4];
                LDSM_X4(bk, Kc_u + klane + (uint32_t)((p*16*KSTR + ks*8) * 4));
                mma_tf32(s[2*p + 0], a, &bk[0]);
                mma_tf32(s[2*p + 1], a, &bk[2]);
            }
        }

        // --- online softmax ---
        float mx0 = -1e30f, mx1 = -1e30f;
        #pragma unroll
        for (int nt = 0; nt < 8; nt++) {
            mx0 = fmaxf(mx0, fmaxf(s[nt][0], s[nt][1]));
            mx1 = fmaxf(mx1, fmaxf(s[nt][2], s[nt][3]));
        }
        mx0 = fmaxf(mx0, __shfl_xor_sync(0xffffffffu, mx0, 1));
        mx0 = fmaxf(mx0, __shfl_xor_sync(0xffffffffu, mx0, 2));
        mx1 = fmaxf(mx1, __shfl_xor_sync(0xffffffffu, mx1, 1));
        mx1 = fmaxf(mx1, __shfl_xor_sync(0xffffffffu, mx1, 2));

        const float mn0 = fmaxf(m0, mx0), mn1 = fmaxf(m1, mx1);
        const float al0 = __expf(m0 - mn0), al1 = __expf(m1 - mn1);

        float sum0 = 0.f, sum1 = 0.f;
        #pragma unroll
        for (int nt = 0; nt < 8; nt++) {
            s[nt][0] = __expf(s[nt][0] - mn0);
            s[nt][1] = __expf(s[nt][1] - mn0);
            s[nt][2] = __expf(s[nt][2] - mn1);
            s[nt][3] = __expf(s[nt][3] - mn1);
            sum0 += s[nt][0] + s[nt][1];
            sum1 += s[nt][2] + s[nt][3];
        }
        sum0 += __shfl_xor_sync(0xffffffffu, sum0, 1);
        sum0 += __shfl_xor_sync(0xffffffffu, sum0, 2);
        sum1 += __shfl_xor_sync(0xffffffffu, sum1, 1);
        sum1 += __shfl_xor_sync(0xffffffffu, sum1, 2);

        l0 = l0 * al0 + sum0;  m0 = mn0;
        l1 = l1 * al1 + sum1;  m1 = mn1;

        #pragma unroll
        for (int nt = 0; nt < 8; nt++) {
            o[nt][0] *= al0; o[nt][1] *= al0;
            o[nt][2] *= al1; o[nt][3] *= al1;
        }

        // --- PV: a-frag via shuffles ---
        #pragma unroll
        for (int ks = 0; ks < 8; ks++) {
            const float e0 = s[ks][0], e1 = s[ks][1], e2 = s[ks][2], e3 = s[ks][3];
            const float v0a = __shfl_sync(0xffffffffu, e0, srcA);
            const float v1a = __shfl_sync(0xffffffffu, e1, srcA);
            const float v0b = __shfl_sync(0xffffffffu, e0, srcB);
            const float v1b = __shfl_sync(0xffffffffu, e1, srcB);
            const float v2a = __shfl_sync(0xffffffffu, e2, srcA);
            const float v3a = __shfl_sync(0xffffffffu, e3, srcA);
            const float v2b = __shfl_sync(0xffffffffu, e2, srcB);
            const float v3b = __shfl_sync(0xffffffffu, e3, srcB);
            uint32_t a[4];
            a[0] = cvt_tf32(hi ? v1a : v0a);
            a[1] = cvt_tf32(hi ? v3a : v2a);
            a[2] = cvt_tf32(hi ? v1b : v0b);
            a[3] = cvt_tf32(hi ? v3b : v2b);
            #pragma unroll
            for (int nt = 0; nt < 8; nt++) {
                uint32_t b[2];
                b[0] = __float_as_uint(Vc[(ks*8 + q)*VSTR     + nt*8 + g]);
                b[1] = __float_as_uint(Vc[(ks*8 + q + 4)*VSTR + nt*8 + g]);
                mma_tf32(o[nt], a, b);
            }
        }
    }

    // normalize + RN-round + write ctx in [B,S,D]
    const float inv0 = 1.f / l0, inv1 = 1.f / l1;
    const int b = bh >> 4, h = bh & 15;
    const int row0 = qt*128 + r0;
    float* dst0 = ctx + ((size_t)(b*SS + row0))*DD + h*64;
    float* dst1 = ctx + ((size_t)(b*SS + row0 + 8))*DD + h*64;
    #pragma unroll
    for (int nt = 0; nt < 8; nt++) {
        float2 w0, w1;
        w0.x = __uint_as_float(cvt_tf32(o[nt][0]*inv0));
        w0.y = __uint_as_float(cvt_tf32(o[nt][1]*inv0));
        w1.x = __uint_as_float(cvt_tf32(o[nt][2]*inv1));
        w1.y = __uint_as_float(cvt_tf32(o[nt][3]*inv1));
        *(float2*)(dst0 + nt*8 + 2*q) = w0;
        *(float2*)(dst1 + nt*8 + 2*q) = w1;
    }
}

// ---------------------------------------------------------------------------
extern "C" void kernel_launch(void* const* d_in, const int* in_sizes, int n_in,
                              void* d_out, int out_size)
{
    const float* x  = (const float*)d_in[0];
    const float* Wq = (const float*)d_in[1];
    const float* bq = (const float*)d_in[2];
    const float* Wk = (const float*)d_in[3];
    const float* bk = (const float*)d_in[4];
    const float* Wv = (const float*)d_in[5];
    const float* bv = (const float*)d_in[6];
    const float* Wo = (const float*)d_in[7];
    const float* bo = (const float*)d_in[8];

    float *q, *k, *v, *ctx, *xr, *wr;
    cudaGetSymbolAddress((void**)&q,   g_q);
    cudaGetSymbolAddress((void**)&k,   g_k);
    cudaGetSymbolAddress((void**)&v,   g_v);
    cudaGetSymbolAddress((void**)&ctx, g_ctx);
    cudaGetSymbolAddress((void**)&xr,  g_xr);
    cudaGetSymbolAddress((void**)&wr,  g_wr);

    const int smem_gemm = 3 * GSTAGE * 2 * sizeof(float);               // 110592
    const int smem_attn = (128*QSTR + 2*KBUF + 2*VBUF) * sizeof(float); // 108544
    cudaFuncSetAttribute(gemm_qkv,
                         cudaFuncAttributeMaxDynamicSharedMemorySize, smem_gemm);
    cudaFuncSetAttribute(gemm_out,
                         cudaFuncAttributeMaxDynamicSharedMemorySize, smem_gemm);
    cudaFuncSetAttribute(attn_mma,
                         cudaFuncAttributeMaxDynamicSharedMemorySize, smem_attn);

    round_prep<<<(XR_F4 + 4*WR_F4) / 256, 256>>>(x, Wq, Wk, Wv, Wo, xr, wr);

    dim3 qkvgrid(DD/128, MM/128, 3);
    gemm_qkv<<<qkvgrid, 256, smem_gemm>>>(xr, wr, bq, bk, bv, q, k, v);

    dim3 agrid(SS/128, BB*HH);
    attn_mma<<<agrid, 256, smem_attn>>>(q, k, v, ctx);

    dim3 ogrid(DD/128, MM/128);
    gemm_out<<<ogrid, 256, smem_gemm>>>(ctx, wr + (size_t)3*DD*DD, bo, (float*)d_out);
}

// round 7
// speedup vs baseline: 2.5073x; 2.5073x over previous
#include <cuda_runtime.h>
#include <cuda_fp16.h>
#include <cstdint>

// Problem constants
#define BB 4
#define SS 2048
#define DD 1024
#define HH 16
#define HD 64
#define MM (BB*SS)   // 8192

// Scratch (all fp16 now)
__device__ __half g_q[BB*HH*SS*HD];
__device__ __half g_k[BB*HH*SS*HD];
__device__ __half g_v[BB*HH*SS*HD];   // TRANSPOSED: [b,h,hd,s]
__device__ __half g_ctx[BB*SS*DD];
__device__ __half g_xr[MM*DD];        // fp16-rounded x
__device__ __half g_wr[4*DD*DD];      // fp16-rounded Wq|Wk|Wv|Wo

// ---------------------------------------------------------------------------
// Helpers (plain-sm_103-legal PTX only)
// ---------------------------------------------------------------------------
__device__ __forceinline__ uint32_t smem_u32(const void* p) {
    uint32_t a;
    asm("{ .reg .u64 t; cvta.to.shared.u64 t, %1; cvt.u32.u64 %0, t; }"
        : "=r"(a) : "l"(p));
    return a;
}

__device__ __forceinline__ void mma_f16(float* d, const uint32_t* a, const uint32_t* b) {
    asm volatile("mma.sync.aligned.m16n8k16.row.col.f32.f16.f16.f32 "
        "{%0,%1,%2,%3}, {%4,%5,%6,%7}, {%8,%9}, {%0,%1,%2,%3};"
        : "+f"(d[0]), "+f"(d[1]), "+f"(d[2]), "+f"(d[3])
        : "r"(a[0]), "r"(a[1]), "r"(a[2]), "r"(a[3]), "r"(b[0]), "r"(b[1]));
}

__device__ __forceinline__ uint32_t h2_bits(__half2 h) {
    uint32_t u;
    memcpy(&u, &h, 4);
    return u;
}

#define CP_ASYNC16(dst, src) \
    asm volatile("cp.async.cg.shared.global [%0], [%1], 16;" :: "r"(dst), "l"(src) : "memory")
#define CP_COMMIT() asm volatile("cp.async.commit_group;" ::: "memory")
#define CP_WAIT0()  asm volatile("cp.async.wait_group 0;" ::: "memory")
#define CP_WAIT1()  asm volatile("cp.async.wait_group 1;" ::: "memory")

// ---------------------------------------------------------------------------
// Prep: RN-round x and the 4 weight matrices to fp16 (once).
// ---------------------------------------------------------------------------
#define XR_F4 (MM*DD/4)
#define WR_F4 (DD*DD/4)

__global__ __launch_bounds__(256)
void round_prep(const float* __restrict__ x,
                const float* __restrict__ Wq, const float* __restrict__ Wk,
                const float* __restrict__ Wv, const float* __restrict__ Wo,
                __half* __restrict__ xr, __half* __restrict__ wr)
{
    const int idx = blockIdx.x * blockDim.x + threadIdx.x;
    const float4* src;
    __half2* dst;
    int off;
    if (idx < XR_F4) {
        src = (const float4*)x; dst = (__half2*)xr; off = idx;
    } else {
        const int t = idx - XR_F4;
        const int sel = t >> 18;
        off = t & (WR_F4 - 1);
        const float* ws = (sel == 0) ? Wq : (sel == 1) ? Wk : (sel == 2) ? Wv : Wo;
        src = (const float4*)ws;
        dst = (__half2*)(wr + (size_t)sel * DD * DD);
    }
    float4 v = src[off];
    dst[2*off + 0] = __floats2half2_rn(v.x, v.y);
    dst[2*off + 1] = __floats2half2_rn(v.z, v.w);
}

// ---------------------------------------------------------------------------
// fp16 warp-MMA GEMM body: C = A[M,1024] @ W[1024,1024]^T + bias
// CTA 128x128, 8 warps (64x32), BK=32 halves (2 k16 steps), 3-stage cp.async.
// MODE 0: half out, [B,H,S,HD] scatter (Q/K)
// MODE 1: half out, TRANSPOSED [B,H,HD,S] scatter (V)
// MODE 2: float out, [M,N] (output projection)
// ---------------------------------------------------------------------------
#define GSTR 40              // halves per row (32 + 8 pad) = 20 words
#define GSTAGE_H (128*GSTR)

template <int MODE>
__device__ __forceinline__
void gemm_body(__half* smemh,
               const __half* __restrict__ A, const __half* __restrict__ W,
               const float* __restrict__ bias, void* __restrict__ Cv)
{
    __half* As = smemh;
    __half* Ws = smemh + 3*GSTAGE_H;
    const uint32_t As_u = smem_u32(As);
    const uint32_t Ws_u = smem_u32(Ws);

    const int tid  = threadIdx.x;
    const int lane = tid & 31, wid = tid >> 5;
    const int q = lane & 3, g = lane >> 2;
    const int mbase = (wid >> 2) * 64;
    const int nbase = (wid & 3) * 32;
    const int rowBase = blockIdx.y * 128;
    const int colBase = blockIdx.x * 128;

    int lrow[2], lcol[2];
    #pragma unroll
    for (int i = 0; i < 2; i++) {
        int c = tid + i*256;         // 0..511 chunks of 8 halves
        lrow[i] = c >> 2;            // 4 chunks per 32-half row
        lcol[i] = (c & 3) * 8;
    }

    float d[4][4][4];
    #pragma unroll
    for (int mt = 0; mt < 4; mt++)
        #pragma unroll
        for (int nt = 0; nt < 4; nt++)
            #pragma unroll
            for (int e = 0; e < 4; e++) d[mt][nt][e] = 0.f;

    auto issue = [&](int kt) {
        const int slot = kt % 3;
        const uint32_t adst = As_u + (uint32_t)(slot * GSTAGE_H) * 2u;
        const uint32_t wdst = Ws_u + (uint32_t)(slot * GSTAGE_H) * 2u;
        #pragma unroll
        for (int i = 0; i < 2; i++) {
            const uint32_t off = (uint32_t)(lrow[i]*GSTR + lcol[i]) * 2u;
            CP_ASYNC16(adst + off, A + (size_t)(rowBase + lrow[i])*DD + kt*32 + lcol[i]);
            CP_ASYNC16(wdst + off, W + (size_t)(colBase + lrow[i])*DD + kt*32 + lcol[i]);
        }
        CP_COMMIT();
    };

    issue(0);
    issue(1);

    for (int kt = 0; kt < 32; kt++) {
        if (kt == 31) CP_WAIT0(); else CP_WAIT1();
        __syncthreads();
        if (kt + 2 < 32) issue(kt + 2);

        const __half* A_s = As + (kt % 3) * GSTAGE_H;
        const __half* W_s = Ws + (kt % 3) * GSTAGE_H;
        #pragma unroll
        for (int ks = 0; ks < 2; ks++) {
            uint32_t af[4][4], bf[4][2];
            #pragma unroll
            for (int mt = 0; mt < 4; mt++) {
                const int r0 = mbase + mt*16 + g;
                af[mt][0] = *(const uint32_t*)(A_s + r0*GSTR     + ks*16 + 2*q);
                af[mt][1] = *(const uint32_t*)(A_s + (r0+8)*GSTR + ks*16 + 2*q);
                af[mt][2] = *(const uint32_t*)(A_s + r0*GSTR     + ks*16 + 2*q + 8);
                af[mt][3] = *(const uint32_t*)(A_s + (r0+8)*GSTR + ks*16 + 2*q + 8);
            }
            #pragma unroll
            for (int nt = 0; nt < 4; nt++) {
                const int n0 = nbase + nt*8 + g;
                bf[nt][0] = *(const uint32_t*)(W_s + n0*GSTR + ks*16 + 2*q);
                bf[nt][1] = *(const uint32_t*)(W_s + n0*GSTR + ks*16 + 2*q + 8);
            }
            #pragma unroll
            for (int mt = 0; mt < 4; mt++)
                #pragma unroll
                for (int nt = 0; nt < 4; nt++)
                    mma_f16(d[mt][nt], af[mt], bf[nt]);
        }
    }

    #pragma unroll
    for (int nt = 0; nt < 4; nt++) {
        const int n0 = colBase + nbase + nt*8 + 2*q;
        const float b0 = bias[n0], b1 = bias[n0 + 1];
        #pragma unroll
        for (int mt = 0; mt < 4; mt++) {
            const int m0 = rowBase + mbase + mt*16 + g;
            #pragma unroll
            for (int half = 0; half < 2; half++) {
                const int m = m0 + half*8;
                const float f0 = d[mt][nt][half*2 + 0] + b0;
                const float f1 = d[mt][nt][half*2 + 1] + b1;
                if (MODE == 2) {
                    float2 o; o.x = f0; o.y = f1;
                    *(float2*)((float*)Cv + (size_t)m*DD + n0) = o;
                } else {
                    const int b  = m >> 11;
                    const int s  = m & (SS - 1);
                    const int h  = n0 >> 6;
                    const int hd = n0 & 63;
                    if (MODE == 0) {
                        __half2 o = __floats2half2_rn(f0, f1);
                        *(__half2*)((__half*)Cv + (((size_t)(b*HH + h)*SS + s)*HD + hd)) = o;
                    } else {   // MODE 1: V transposed [b,h,hd,s]
                        __half* Cp = (__half*)Cv + ((size_t)(b*HH + h)*HD + hd)*SS + s;
                        Cp[0]  = __float2half_rn(f0);
                        Cp[SS] = __float2half_rn(f1);
                    }
                }
            }
        }
    }
}

__global__ __launch_bounds__(256, 2)
void gemm_qkv(const __half* __restrict__ A, const __half* __restrict__ Wr,
              const float* __restrict__ b0, const float* __restrict__ b1,
              const float* __restrict__ b2,
              __half* __restrict__ C0, __half* __restrict__ C1, __half* __restrict__ C2)
{
    extern __shared__ __half smemh[];
    const int z = blockIdx.z;
    const __half* W = Wr + (size_t)z * DD * DD;
    if (z == 2) {
        gemm_body<1>(smemh, A, W, b2, C2);
    } else {
        const float* b = (z == 0) ? b0 : b1;
        __half*      C = (z == 0) ? C0 : C1;
        gemm_body<0>(smemh, A, W, b, C);
    }
}

__global__ __launch_bounds__(256, 2)
void gemm_out(const __half* __restrict__ A, const __half* __restrict__ W,
              const float* __restrict__ bias, float* __restrict__ C)
{
    extern __shared__ __half smemh[];
    gemm_body<2>(smemh, A, W, bias, C);
}

// ---------------------------------------------------------------------------
// fp16 warp-MMA flash-attention.
// Q resident [128][72] halves; K [2][64][72] (keys x d); V [2][64][72]
// TRANSPOSED tile (d x keys) double-buffered via cp.async.
// QK^T and PV via m16n8k16; P c-frag -> a-frag needs only half2 packs.
// ---------------------------------------------------------------------------
#define ASTR 72              // halves per row = 36 words
#define AKBUF (64*ASTR)

__global__ __launch_bounds__(256, 2)
void attn_mma(const __half* __restrict__ Q, const __half* __restrict__ K,
              const __half* __restrict__ Vt, __half* __restrict__ ctx)
{
    extern __shared__ __half sh[];
    __half* Qs = sh;                   // [128][72]
    __half* Ks = sh + 128*ASTR;        // [2][64][72]
    __half* Vs = Ks + 2*AKBUF;         // [2][64][72] (d-major)
    const uint32_t Ks_u = smem_u32(Ks);
    const uint32_t Vs_u = smem_u32(Vs);

    const int tid  = threadIdx.x;
    const int lane = tid & 31, wid = tid >> 5;
    const int q = lane & 3, g = lane >> 2;
    const int bh = blockIdx.y, qt = blockIdx.x;

    const __half* Qb = Q  + (size_t)bh*SS*HD + (size_t)qt*128*HD;
    const __half* Kb = K  + (size_t)bh*SS*HD;
    const __half* Vb = Vt + (size_t)bh*HD*SS;   // [hd][s]

    // Q: load, scale by 1/8 (exact), store. 1024 chunks of 8 halves.
    const __half2 sc = __half2half2(__float2half(0.125f));
    #pragma unroll
    for (int i = 0; i < 4; i++) {
        const int c = tid + i*256;
        const int r = c >> 3, c8 = (c & 7) * 8;
        uint4 raw = *(const uint4*)(Qb + r*HD + c8);
        __half2* p = (__half2*)&raw;
        p[0] = __hmul2(p[0], sc); p[1] = __hmul2(p[1], sc);
        p[2] = __hmul2(p[2], sc); p[3] = __hmul2(p[3], sc);
        *(uint4*)(Qs + r*ASTR + c8) = raw;
    }

    auto issue_kv = [&](int kt) {
        const int buf = kt & 1;
        #pragma unroll
        for (int i = 0; i < 2; i++) {
            const int c = tid + i*256;       // 512 chunks of 8 halves
            const int r = c >> 3, c8 = (c & 7) * 8;
            const uint32_t off = (uint32_t)(buf*AKBUF + r*ASTR + c8) * 2u;
            CP_ASYNC16(Ks_u + off, Kb + (size_t)(kt*64 + r)*HD + c8);
            CP_ASYNC16(Vs_u + off, Vb + (size_t)r*SS + kt*64 + c8);
        }
        CP_COMMIT();
    };

    const int r0 = wid*16 + g;

    float m0 = -1e30f, m1 = -1e30f, l0 = 0.f, l1 = 0.f;
    float o[8][4];
    #pragma unroll
    for (int nt = 0; nt < 8; nt++)
        #pragma unroll
        for (int e = 0; e < 4; e++) o[nt][e] = 0.f;

    issue_kv(0);

    for (int kt = 0; kt < SS/64; kt++) {
        CP_WAIT0();
        __syncthreads();
        if (kt + 1 < SS/64) issue_kv(kt + 1);

        const __half* Kc = Ks + (kt & 1) * AKBUF;
        const __half* Vc = Vs + (kt & 1) * AKBUF;

        // --- QK^T: S stripe [16][64] per warp ---
        float s[8][4];
        #pragma unroll
        for (int nt = 0; nt < 8; nt++)
            #pragma unroll
            for (int e = 0; e < 4; e++) s[nt][e] = 0.f;

        #pragma unroll
        for (int ks = 0; ks < 4; ks++) {
            uint32_t a[4];
            a[0] = *(const uint32_t*)(Qs + r0*ASTR     + ks*16 + 2*q);
            a[1] = *(const uint32_t*)(Qs + (r0+8)*ASTR + ks*16 + 2*q);
            a[2] = *(const uint32_t*)(Qs + r0*ASTR     + ks*16 + 2*q + 8);
            a[3] = *(const uint32_t*)(Qs + (r0+8)*ASTR + ks*16 + 2*q + 8);
            #pragma unroll
            for (int p = 0; p < 8; p++) {
                uint32_t b[2];
                b[0] = *(const uint32_t*)(Kc + (p*8 + g)*ASTR + ks*16 + 2*q);
                b[1] = *(const uint32_t*)(Kc + (p*8 + g)*ASTR + ks*16 + 2*q + 8);
                mma_f16(s[p], a, b);
            }
        }

        // --- online softmax (rows r0, r0+8; 4 lanes per row) ---
        float mx0 = -1e30f, mx1 = -1e30f;
        #pragma unroll
        for (int nt = 0; nt < 8; nt++) {
            mx0 = fmaxf(mx0, fmaxf(s[nt][0], s[nt][1]));
            mx1 = fmaxf(mx1, fmaxf(s[nt][2], s[nt][3]));
        }
        mx0 = fmaxf(mx0, __shfl_xor_sync(0xffffffffu, mx0, 1));
        mx0 = fmaxf(mx0, __shfl_xor_sync(0xffffffffu, mx0, 2));
        mx1 = fmaxf(mx1, __shfl_xor_sync(0xffffffffu, mx1, 1));
        mx1 = fmaxf(mx1, __shfl_xor_sync(0xffffffffu, mx1, 2));

        const float mn0 = fmaxf(m0, mx0), mn1 = fmaxf(m1, mx1);
        const float al0 = __expf(m0 - mn0), al1 = __expf(m1 - mn1);

        float sum0 = 0.f, sum1 = 0.f;
        #pragma unroll
        for (int nt = 0; nt < 8; nt++) {
            s[nt][0] = __expf(s[nt][0] - mn0);
            s[nt][1] = __expf(s[nt][1] - mn0);
            s[nt][2] = __expf(s[nt][2] - mn1);
            s[nt][3] = __expf(s[nt][3] - mn1);
            sum0 += s[nt][0] + s[nt][1];
            sum1 += s[nt][2] + s[nt][3];
        }
        sum0 += __shfl_xor_sync(0xffffffffu, sum0, 1);
        sum0 += __shfl_xor_sync(0xffffffffu, sum0, 2);
        sum1 += __shfl_xor_sync(0xffffffffu, sum1, 1);
        sum1 += __shfl_xor_sync(0xffffffffu, sum1, 2);

        l0 = l0 * al0 + sum0;  m0 = mn0;
        l1 = l1 * al1 + sum1;  m1 = mn1;

        #pragma unroll
        for (int nt = 0; nt < 8; nt++) {
            o[nt][0] *= al0; o[nt][1] *= al0;
            o[nt][2] *= al1; o[nt][3] *= al1;
        }

        // --- PV: P a-frags are direct half2 packs of the S c-frags ---
        #pragma unroll
        for (int ks = 0; ks < 4; ks++) {
            uint32_t a[4];
            a[0] = h2_bits(__floats2half2_rn(s[2*ks][0],   s[2*ks][1]));
            a[1] = h2_bits(__floats2half2_rn(s[2*ks][2],   s[2*ks][3]));
            a[2] = h2_bits(__floats2half2_rn(s[2*ks+1][0], s[2*ks+1][1]));
            a[3] = h2_bits(__floats2half2_rn(s[2*ks+1][2], s[2*ks+1][3]));
            #pragma unroll
            for (int nt = 0; nt < 8; nt++) {
                uint32_t b[2];
                b[0] = *(const uint32_t*)(Vc + (nt*8 + g)*ASTR + ks*16 + 2*q);
                b[1] = *(const uint32_t*)(Vc + (nt*8 + g)*ASTR + ks*16 + 2*q + 8);
                mma_f16(o[nt], a, b);
            }
        }
    }

    // normalize + RN-round + write ctx (fp16) in [B,S,D]
    const float inv0 = 1.f / l0, inv1 = 1.f / l1;
    const int b = bh >> 4, h = bh & 15;
    const int row0 = qt*128 + r0;
    __half* dst0 = ctx + ((size_t)(b*SS + row0))*DD + h*64;
    __half* dst1 = ctx + ((size_t)(b*SS + row0 + 8))*DD + h*64;
    #pragma unroll
    for (int nt = 0; nt < 8; nt++) {
        *(__half2*)(dst0 + nt*8 + 2*q) = __floats2half2_rn(o[nt][0]*inv0, o[nt][1]*inv0);
        *(__half2*)(dst1 + nt*8 + 2*q) = __floats2half2_rn(o[nt][2]*inv1, o[nt][3]*inv1);
    }
}

// ---------------------------------------------------------------------------
extern "C" void kernel_launch(void* const* d_in, const int* in_sizes, int n_in,
                              void* d_out, int out_size)
{
    const float* x  = (const float*)d_in[0];
    const float* Wq = (const float*)d_in[1];
    const float* bq = (const float*)d_in[2];
    const float* Wk = (const float*)d_in[3];
    const float* bk = (const float*)d_in[4];
    const float* Wv = (const float*)d_in[5];
    const float* bv = (const float*)d_in[6];
    const float* Wo = (const float*)d_in[7];
    const float* bo = (const float*)d_in[8];

    __half *q, *k, *v, *ctx, *xr, *wr;
    cudaGetSymbolAddress((void**)&q,   g_q);
    cudaGetSymbolAddress((void**)&k,   g_k);
    cudaGetSymbolAddress((void**)&v,   g_v);
    cudaGetSymbolAddress((void**)&ctx, g_ctx);
    cudaGetSymbolAddress((void**)&xr,  g_xr);
    cudaGetSymbolAddress((void**)&wr,  g_wr);

    const int smem_gemm = 3 * 2 * GSTAGE_H * (int)sizeof(__half);        // 61440
    const int smem_attn = (128*ASTR + 4*AKBUF) * (int)sizeof(__half);    // 55296
    cudaFuncSetAttribute(gemm_qkv,
                         cudaFuncAttributeMaxDynamicSharedMemorySize, smem_gemm);
    cudaFuncSetAttribute(gemm_out,
                         cudaFuncAttributeMaxDynamicSharedMemorySize, smem_gemm);
    cudaFuncSetAttribute(attn_mma,
                         cudaFuncAttributeMaxDynamicSharedMemorySize, smem_attn);

    round_prep<<<(XR_F4 + 4*WR_F4) / 256, 256>>>(x, Wq, Wk, Wv, Wo, xr, wr);

    dim3 qkvgrid(DD/128, MM/128, 3);
    gemm_qkv<<<qkvgrid, 256, smem_gemm>>>(xr, wr, bq, bk, bv, q, k, v);

    dim3 agrid(SS/128, BB*HH);
    attn_mma<<<agrid, 256, smem_attn>>>(q, k, v, ctx);

    dim3 ogrid(DD/128, MM/128);
    gemm_out<<<ogrid, 256, smem_gemm>>>(ctx, wr + (size_t)3*DD*DD, bo, (float*)d_out);
}

// round 8
// speedup vs baseline: 2.7595x; 1.1006x over previous
#include <cuda_runtime.h>
#include <cuda_fp16.h>
#include <cstdint>

// Problem constants
#define BB 4
#define SS 2048
#define DD 1024
#define HH 16
#define HD 64
#define MM (BB*SS)   // 8192

// Q pre-scale: 1/sqrt(64) * log2(e)  (scores emerge in log2 units)
#define QSCALE 0.18033688011112042f

// Scratch
__device__ __half g_q[BB*HH*SS*HD];
__device__ __half g_k[BB*HH*SS*HD];
__device__ __half g_v[BB*HH*SS*HD];   // TRANSPOSED: [b,h,hd,s]
__device__ __half g_ctx[BB*SS*DD];
__device__ __half g_xr[MM*DD];
__device__ __half g_wr[4*DD*DD];

// ---------------------------------------------------------------------------
// Helpers (plain-sm_103-legal PTX only)
// ---------------------------------------------------------------------------
__device__ __forceinline__ uint32_t smem_u32(const void* p) {
    uint32_t a;
    asm("{ .reg .u64 t; cvta.to.shared.u64 t, %1; cvt.u32.u64 %0, t; }"
        : "=r"(a) : "l"(p));
    return a;
}

__device__ __forceinline__ void mma_f16(float* d, const uint32_t* a, const uint32_t* b) {
    asm volatile("mma.sync.aligned.m16n8k16.row.col.f32.f16.f16.f32 "
        "{%0,%1,%2,%3}, {%4,%5,%6,%7}, {%8,%9}, {%0,%1,%2,%3};"
        : "+f"(d[0]), "+f"(d[1]), "+f"(d[2]), "+f"(d[3])
        : "r"(a[0]), "r"(a[1]), "r"(a[2]), "r"(a[3]), "r"(b[0]), "r"(b[1]));
}

__device__ __forceinline__ uint32_t h2_bits(__half2 h) {
    uint32_t u;
    memcpy(&u, &h, 4);
    return u;
}

#define CP_ASYNC16(dst, src) \
    asm volatile("cp.async.cg.shared.global [%0], [%1], 16;" :: "r"(dst), "l"(src) : "memory")
#define CP_COMMIT() asm volatile("cp.async.commit_group;" ::: "memory")
#define CP_WAIT0()  asm volatile("cp.async.wait_group 0;" ::: "memory")

// ---------------------------------------------------------------------------
// Prep: RN-round x and the 4 weight matrices to fp16 (once).
// ---------------------------------------------------------------------------
#define XR_F4 (MM*DD/4)
#define WR_F4 (DD*DD/4)

__global__ __launch_bounds__(256)
void round_prep(const float* __restrict__ x,
                const float* __restrict__ Wq, const float* __restrict__ Wk,
                const float* __restrict__ Wv, const float* __restrict__ Wo,
                __half* __restrict__ xr, __half* __restrict__ wr)
{
    const int idx = blockIdx.x * blockDim.x + threadIdx.x;
    const float4* src;
    __half2* dst;
    int off;
    if (idx < XR_F4) {
        src = (const float4*)x; dst = (__half2*)xr; off = idx;
    } else {
        const int t = idx - XR_F4;
        const int sel = t >> 18;
        off = t & (WR_F4 - 1);
        const float* ws = (sel == 0) ? Wq : (sel == 1) ? Wk : (sel == 2) ? Wv : Wo;
        src = (const float4*)ws;
        dst = (__half2*)(wr + (size_t)sel * DD * DD);
    }
    float4 v = src[off];
    dst[2*off + 0] = __floats2half2_rn(v.x, v.y);
    dst[2*off + 1] = __floats2half2_rn(v.z, v.w);
}

// ---------------------------------------------------------------------------
// fp16 warp-MMA GEMM: C = A[M,1024] @ W[1024,1024]^T + bias (then *oscale)
// CTA 128x128, 8 warps (64x32), BK=64 halves (4 k16 steps), 2-stage cp.async.
// MODE 0: half out, [B,H,S,HD] scatter (Q/K)   MODE 1: V transposed [B,H,HD,S]
// MODE 2: float out, [M,N]
// ---------------------------------------------------------------------------
#define GSTR 72              // halves per row (64 + 8 pad) = 36 words
#define GSTAGE_H (128*GSTR)

template <int MODE>
__device__ __forceinline__
void gemm_body(__half* smemh,
               const __half* __restrict__ A, const __half* __restrict__ W,
               const float* __restrict__ bias, void* __restrict__ Cv, float oscale)
{
    __half* As = smemh;
    __half* Ws = smemh + 2*GSTAGE_H;
    const uint32_t As_u = smem_u32(As);
    const uint32_t Ws_u = smem_u32(Ws);

    const int tid  = threadIdx.x;
    const int lane = tid & 31, wid = tid >> 5;
    const int q = lane & 3, g = lane >> 2;
    const int mbase = (wid >> 2) * 64;
    const int nbase = (wid & 3) * 32;
    const int rowBase = blockIdx.y * 128;
    const int colBase = blockIdx.x * 128;

    int lrow[4], lcol[4];
    #pragma unroll
    for (int i = 0; i < 4; i++) {
        int c = tid + i*256;         // 0..1023 chunks of 8 halves
        lrow[i] = c >> 3;            // 8 chunks per 64-half row
        lcol[i] = (c & 7) * 8;
    }

    float d[4][4][4];
    #pragma unroll
    for (int mt = 0; mt < 4; mt++)
        #pragma unroll
        for (int nt = 0; nt < 4; nt++)
            #pragma unroll
            for (int e = 0; e < 4; e++) d[mt][nt][e] = 0.f;

    auto issue = [&](int kt) {
        const int slot = kt & 1;
        const uint32_t adst = As_u + (uint32_t)(slot * GSTAGE_H) * 2u;
        const uint32_t wdst = Ws_u + (uint32_t)(slot * GSTAGE_H) * 2u;
        #pragma unroll
        for (int i = 0; i < 4; i++) {
            const uint32_t off = (uint32_t)(lrow[i]*GSTR + lcol[i]) * 2u;
            CP_ASYNC16(adst + off, A + (size_t)(rowBase + lrow[i])*DD + kt*64 + lcol[i]);
            CP_ASYNC16(wdst + off, W + (size_t)(colBase + lrow[i])*DD + kt*64 + lcol[i]);
        }
        CP_COMMIT();
    };

    issue(0);

    for (int kt = 0; kt < 16; kt++) {
        CP_WAIT0();
        __syncthreads();
        if (kt + 1 < 16) issue(kt + 1);

        const __half* A_s = As + (kt & 1) * GSTAGE_H;
        const __half* W_s = Ws + (kt & 1) * GSTAGE_H;
        #pragma unroll
        for (int ks = 0; ks < 4; ks++) {
            uint32_t af[4][4], bf[4][2];
            #pragma unroll
            for (int mt = 0; mt < 4; mt++) {
                const int r0 = mbase + mt*16 + g;
                af[mt][0] = *(const uint32_t*)(A_s + r0*GSTR     + ks*16 + 2*q);
                af[mt][1] = *(const uint32_t*)(A_s + (r0+8)*GSTR + ks*16 + 2*q);
                af[mt][2] = *(const uint32_t*)(A_s + r0*GSTR     + ks*16 + 2*q + 8);
                af[mt][3] = *(const uint32_t*)(A_s + (r0+8)*GSTR + ks*16 + 2*q + 8);
            }
            #pragma unroll
            for (int nt = 0; nt < 4; nt++) {
                const int n0 = nbase + nt*8 + g;
                bf[nt][0] = *(const uint32_t*)(W_s + n0*GSTR + ks*16 + 2*q);
                bf[nt][1] = *(const uint32_t*)(W_s + n0*GSTR + ks*16 + 2*q + 8);
            }
            #pragma unroll
            for (int mt = 0; mt < 4; mt++)
                #pragma unroll
                for (int nt = 0; nt < 4; nt++)
                    mma_f16(d[mt][nt], af[mt], bf[nt]);
        }
    }

    #pragma unroll
    for (int nt = 0; nt < 4; nt++) {
        const int n0 = colBase + nbase + nt*8 + 2*q;
        const float b0 = bias[n0], b1 = bias[n0 + 1];
        #pragma unroll
        for (int mt = 0; mt < 4; mt++) {
            const int m0 = rowBase + mbase + mt*16 + g;
            #pragma unroll
            for (int half = 0; half < 2; half++) {
                const int m = m0 + half*8;
                const float f0 = (d[mt][nt][half*2 + 0] + b0) * oscale;
                const float f1 = (d[mt][nt][half*2 + 1] + b1) * oscale;
                if (MODE == 2) {
                    float2 o; o.x = f0; o.y = f1;
                    *(float2*)((float*)Cv + (size_t)m*DD + n0) = o;
                } else {
                    const int b  = m >> 11;
                    const int s  = m & (SS - 1);
                    const int h  = n0 >> 6;
                    const int hd = n0 & 63;
                    if (MODE == 0) {
                        __half2 o = __floats2half2_rn(f0, f1);
                        *(__half2*)((__half*)Cv + (((size_t)(b*HH + h)*SS + s)*HD + hd)) = o;
                    } else {   // MODE 1: V transposed [b,h,hd,s]
                        __half* Cp = (__half*)Cv + ((size_t)(b*HH + h)*HD + hd)*SS + s;
                        Cp[0]  = __float2half_rn(f0);
                        Cp[SS] = __float2half_rn(f1);
                    }
                }
            }
        }
    }
}

__global__ __launch_bounds__(256, 2)
void gemm_qkv(const __half* __restrict__ A, const __half* __restrict__ Wr,
              const float* __restrict__ b0, const float* __restrict__ b1,
              const float* __restrict__ b2,
              __half* __restrict__ C0, __half* __restrict__ C1, __half* __restrict__ C2)
{
    extern __shared__ __half smemh[];
    const int z = blockIdx.z;
    const __half* W = Wr + (size_t)z * DD * DD;
    if (z == 2) {
        gemm_body<1>(smemh, A, W, b2, C2, 1.0f);
    } else if (z == 0) {
        gemm_body<0>(smemh, A, W, b0, C0, QSCALE);   // Q pre-scaled into log2 units
    } else {
        gemm_body<0>(smemh, A, W, b1, C1, 1.0f);
    }
}

__global__ __launch_bounds__(256, 2)
void gemm_out(const __half* __restrict__ A, const __half* __restrict__ W,
              const float* __restrict__ bias, float* __restrict__ C)
{
    extern __shared__ __half smemh[];
    gemm_body<2>(smemh, A, W, bias, C, 1.0f);
}

// ---------------------------------------------------------------------------
// fp16 warp-MMA flash-attention, exp2/f16x2 softmax + ones-MMA row sums.
// Scores arrive in log2 units (Q pre-scaled in projection).
// ---------------------------------------------------------------------------
#define ASTR 72
#define AKBUF (64*ASTR)

__global__ __launch_bounds__(256, 2)
void attn_mma(const __half* __restrict__ Q, const __half* __restrict__ K,
              const __half* __restrict__ Vt, __half* __restrict__ ctx)
{
    extern __shared__ __half sh[];
    __half* Qs = sh;                   // [128][72]
    __half* Ks = sh + 128*ASTR;        // [2][64][72]
    __half* Vs = Ks + 2*AKBUF;         // [2][64][72] (d-major)
    const uint32_t Qs_u = smem_u32(Qs);
    const uint32_t Ks_u = smem_u32(Ks);
    const uint32_t Vs_u = smem_u32(Vs);

    const int tid  = threadIdx.x;
    const int lane = tid & 31, wid = tid >> 5;
    const int q = lane & 3, g = lane >> 2;
    const int bh = blockIdx.y, qt = blockIdx.x;

    const __half* Qb = Q  + (size_t)bh*SS*HD + (size_t)qt*128*HD;
    const __half* Kb = K  + (size_t)bh*SS*HD;
    const __half* Vb = Vt + (size_t)bh*HD*SS;   // [hd][s]

    auto issue_kv = [&](int kt) {
        const int buf = kt & 1;
        #pragma unroll
        for (int i = 0; i < 2; i++) {
            const int c = tid + i*256;
            const int r = c >> 3, c8 = (c & 7) * 8;
            const uint32_t off = (uint32_t)(buf*AKBUF + r*ASTR + c8) * 2u;
            CP_ASYNC16(Ks_u + off, Kb + (size_t)(kt*64 + r)*HD + c8);
            CP_ASYNC16(Vs_u + off, Vb + (size_t)r*SS + kt*64 + c8);
        }
        CP_COMMIT();
    };

    // Q via cp.async (pre-scaled in projection) — joins kv(0)'s group
    #pragma unroll
    for (int i = 0; i < 4; i++) {
        const int c = tid + i*256;
        const int r = c >> 3, c8 = (c & 7) * 8;
        CP_ASYNC16(Qs_u + (uint32_t)(r*ASTR + c8)*2u, Qb + r*HD + c8);
    }
    issue_kv(0);

    const int r0 = wid*16 + g;

    float m0 = -1e30f, m1 = -1e30f, l0 = 0.f, l1 = 0.f;
    float o[8][4];
    #pragma unroll
    for (int nt = 0; nt < 8; nt++)
        #pragma unroll
        for (int e = 0; e < 4; e++) o[nt][e] = 0.f;

    const uint32_t bones = 0x3C003C00u;       // half2(1,1)
    const uint32_t bo2[2] = { bones, bones };

    for (int kt = 0; kt < SS/64; kt++) {
        CP_WAIT0();
        __syncthreads();
        if (kt + 1 < SS/64) issue_kv(kt + 1);

        const __half* Kc = Ks + (kt & 1) * AKBUF;
        const __half* Vc = Vs + (kt & 1) * AKBUF;

        // --- QK^T: S stripe [16][64] per warp (log2 units) ---
        float s[8][4];
        #pragma unroll
        for (int nt = 0; nt < 8; nt++)
            #pragma unroll
            for (int e = 0; e < 4; e++) s[nt][e] = 0.f;

        #pragma unroll
        for (int ks = 0; ks < 4; ks++) {
            uint32_t a[4];
            a[0] = *(const uint32_t*)(Qs + r0*ASTR     + ks*16 + 2*q);
            a[1] = *(const uint32_t*)(Qs + (r0+8)*ASTR + ks*16 + 2*q);
            a[2] = *(const uint32_t*)(Qs + r0*ASTR     + ks*16 + 2*q + 8);
            a[3] = *(const uint32_t*)(Qs + (r0+8)*ASTR + ks*16 + 2*q + 8);
            #pragma unroll
            for (int p = 0; p < 8; p++) {
                uint32_t b[2];
                b[0] = *(const uint32_t*)(Kc + (p*8 + g)*ASTR + ks*16 + 2*q);
                b[1] = *(const uint32_t*)(Kc + (p*8 + g)*ASTR + ks*16 + 2*q + 8);
                mma_f16(s[p], a, b);
            }
        }

        // --- online softmax (log2 domain) ---
        float mx0 = -1e30f, mx1 = -1e30f;
        #pragma unroll
        for (int nt = 0; nt < 8; nt++) {
            mx0 = fmaxf(mx0, fmaxf(s[nt][0], s[nt][1]));
            mx1 = fmaxf(mx1, fmaxf(s[nt][2], s[nt][3]));
        }
        mx0 = fmaxf(mx0, __shfl_xor_sync(0xffffffffu, mx0, 1));
        mx0 = fmaxf(mx0, __shfl_xor_sync(0xffffffffu, mx0, 2));
        mx1 = fmaxf(mx1, __shfl_xor_sync(0xffffffffu, mx1, 1));
        mx1 = fmaxf(mx1, __shfl_xor_sync(0xffffffffu, mx1, 2));

        const float mn0 = fmaxf(m0, mx0), mn1 = fmaxf(m1, mx1);
        const float al0 = exp2f(m0 - mn0), al1 = exp2f(m1 - mn1);
        m0 = mn0; m1 = mn1;

        #pragma unroll
        for (int nt = 0; nt < 8; nt++) {
            o[nt][0] *= al0; o[nt][1] *= al0;
            o[nt][2] *= al1; o[nt][3] *= al1;
        }

        // --- P = exp2(s - mn) in f16x2; PV + ones-MMA row sums ---
        float lc[4] = {0.f, 0.f, 0.f, 0.f};
        #pragma unroll
        for (int ks = 0; ks < 4; ks++) {
            uint32_t a[4];
            a[0] = h2_bits(h2exp2(__floats2half2_rn(s[2*ks][0]   - mn0, s[2*ks][1]   - mn0)));
            a[1] = h2_bits(h2exp2(__floats2half2_rn(s[2*ks][2]   - mn1, s[2*ks][3]   - mn1)));
            a[2] = h2_bits(h2exp2(__floats2half2_rn(s[2*ks+1][0] - mn0, s[2*ks+1][1] - mn0)));
            a[3] = h2_bits(h2exp2(__floats2half2_rn(s[2*ks+1][2] - mn1, s[2*ks+1][3] - mn1)));
            mma_f16(lc, a, bo2);           // row sums (constant ones b-frag)
            #pragma unroll
            for (int nt = 0; nt < 8; nt++) {
                uint32_t b[2];
                b[0] = *(const uint32_t*)(Vc + (nt*8 + g)*ASTR + ks*16 + 2*q);
                b[1] = *(const uint32_t*)(Vc + (nt*8 + g)*ASTR + ks*16 + 2*q + 8);
                mma_f16(o[nt], a, b);
            }
        }
        l0 = l0 * al0 + lc[0];
        l1 = l1 * al1 + lc[2];
    }

    // normalize + RN-round + write ctx (fp16) in [B,S,D]
    const float inv0 = 1.f / l0, inv1 = 1.f / l1;
    const int b = bh >> 4, h = bh & 15;
    const int row0 = qt*128 + r0;
    __half* dst0 = ctx + ((size_t)(b*SS + row0))*DD + h*64;
    __half* dst1 = ctx + ((size_t)(b*SS + row0 + 8))*DD + h*64;
    #pragma unroll
    for (int nt = 0; nt < 8; nt++) {
        *(__half2*)(dst0 + nt*8 + 2*q) = __floats2half2_rn(o[nt][0]*inv0, o[nt][1]*inv0);
        *(__half2*)(dst1 + nt*8 + 2*q) = __floats2half2_rn(o[nt][2]*inv1, o[nt][3]*inv1);
    }
}

// ---------------------------------------------------------------------------
extern "C" void kernel_launch(void* const* d_in, const int* in_sizes, int n_in,
                              void* d_out, int out_size)
{
    const float* x  = (const float*)d_in[0];
    const float* Wq = (const float*)d_in[1];
    const float* bq = (const float*)d_in[2];
    const float* Wk = (const float*)d_in[3];
    const float* bk = (const float*)d_in[4];
    const float* Wv = (const float*)d_in[5];
    const float* bv = (const float*)d_in[6];
    const float* Wo = (const float*)d_in[7];
    const float* bo = (const float*)d_in[8];

    __half *q, *k, *v, *ctx, *xr, *wr;
    cudaGetSymbolAddress((void**)&q,   g_q);
    cudaGetSymbolAddress((void**)&k,   g_k);
    cudaGetSymbolAddress((void**)&v,   g_v);
    cudaGetSymbolAddress((void**)&ctx, g_ctx);
    cudaGetSymbolAddress((void**)&xr,  g_xr);
    cudaGetSymbolAddress((void**)&wr,  g_wr);

    const int smem_gemm = 2 * 2 * GSTAGE_H * (int)sizeof(__half);        // 73728
    const int smem_attn = (128*ASTR + 4*AKBUF) * (int)sizeof(__half);    // 55296
    cudaFuncSetAttribute(gemm_qkv,
                         cudaFuncAttributeMaxDynamicSharedMemorySize, smem_gemm);
    cudaFuncSetAttribute(gemm_out,
                         cudaFuncAttributeMaxDynamicSharedMemorySize, smem_gemm);
    cudaFuncSetAttribute(attn_mma,
                         cudaFuncAttributeMaxDynamicSharedMemorySize, smem_attn);

    round_prep<<<(XR_F4 + 4*WR_F4) / 256, 256>>>(x, Wq, Wk, Wv, Wo, xr, wr);

    dim3 qkvgrid(DD/128, MM/128, 3);
    gemm_qkv<<<qkvgrid, 256, smem_gemm>>>(xr, wr, bq, bk, bv, q, k, v);

    dim3 agrid(SS/128, BB*HH);
    attn_mma<<<agrid, 256, smem_attn>>>(q, k, v, ctx);

    dim3 ogrid(DD/128, MM/128);
    gemm_out<<<ogrid, 256, smem_gemm>>>(ctx, wr + (size_t)3*DD*DD, bo, (float*)d_out);
}

// round 9
// speedup vs baseline: 2.8962x; 1.0495x over previous
#include <cuda_runtime.h>
#include <cuda_fp16.h>
#include <cstdint>

// Problem constants
#define BB 4
#define SS 2048
#define DD 1024
#define HH 16
#define HD 64
#define MM (BB*SS)   // 8192

// Q pre-scale: 1/sqrt(64) * log2(e)
#define QSCALE 0.18033688011112042f

// Scratch
__device__ __half g_q[BB*HH*SS*HD];   // hd sigma-permuted
__device__ __half g_k[BB*HH*SS*HD];   // hd sigma-permuted
__device__ __half g_v[BB*HH*SS*HD];   // TRANSPOSED [b,h,hd,s], s sigma-permuted
__device__ __half g_ctx[BB*SS*DD];    // D columns sigma-permuted
__device__ __half g_xr[MM*DD];        // k-dim sigma-permuted
__device__ __half g_wr[4*DD*DD];      // k-dim sigma-permuted

// ---------------------------------------------------------------------------
// Helpers
// ---------------------------------------------------------------------------
__device__ __forceinline__ uint32_t smem_u32(const void* p) {
    uint32_t a;
    asm("{ .reg .u64 t; cvta.to.shared.u64 t, %1; cvt.u32.u64 %0, t; }"
        : "=r"(a) : "l"(p));
    return a;
}

// pair-interleave permutation within a 16-group:
// j = 2q + delta + 8*eps  ->  4q + 2*eps + delta
__device__ __forceinline__ int sig16(int j) {
    return ((j & 6) << 1) | ((j >> 3) << 1) | (j & 1);
}

__device__ __forceinline__ void mma_f16(float* d, const uint32_t* a, const uint32_t* b) {
    asm volatile("mma.sync.aligned.m16n8k16.row.col.f32.f16.f16.f32 "
        "{%0,%1,%2,%3}, {%4,%5,%6,%7}, {%8,%9}, {%0,%1,%2,%3};"
        : "+f"(d[0]), "+f"(d[1]), "+f"(d[2]), "+f"(d[3])
        : "r"(a[0]), "r"(a[1]), "r"(a[2]), "r"(a[3]), "r"(b[0]), "r"(b[1]));
}

__device__ __forceinline__ uint32_t h2_bits(__half2 h) {
    uint32_t u;
    memcpy(&u, &h, 4);
    return u;
}

#define CP_ASYNC16(dst, src) \
    asm volatile("cp.async.cg.shared.global [%0], [%1], 16;" :: "r"(dst), "l"(src) : "memory")
#define CP_COMMIT() asm volatile("cp.async.commit_group;" ::: "memory")
#define CP_WAIT0()  asm volatile("cp.async.wait_group 0;" ::: "memory")

// ---------------------------------------------------------------------------
// Prep: RN-round to fp16 AND sigma-permute the k-dim (inner 1024) once.
// ---------------------------------------------------------------------------
#define XR_F4 (MM*DD/4)
#define WR_F4 (DD*DD/4)

__global__ __launch_bounds__(256)
void round_prep(const float* __restrict__ x,
                const float* __restrict__ Wq, const float* __restrict__ Wk,
                const float* __restrict__ Wv, const float* __restrict__ Wo,
                __half* __restrict__ xr, __half* __restrict__ wr)
{
    const int idx = blockIdx.x * blockDim.x + threadIdx.x;
    const float4* src;
    __half* dstb;
    int off;
    if (idx < XR_F4) {
        src = (const float4*)x; dstb = xr; off = idx;
    } else {
        const int t = idx - XR_F4;
        const int sel = t >> 18;
        off = t & (WR_F4 - 1);
        const float* ws = (sel == 0) ? Wq : (sel == 1) ? Wk : (sel == 2) ? Wv : Wo;
        src = (const float4*)ws;
        dstb = wr + (size_t)sel * DD * DD;
    }
    float4 v = src[off];
    const int row  = off >> 8;             // DD/4 = 256 float4 per row
    const int col  = (off & 255) * 4;
    const int base = row * DD + (col & ~15);
    const int j    = col & 15;              // 0,4,8,12 (even)
    *(__half2*)(dstb + base + sig16(j))     = __floats2half2_rn(v.x, v.y);
    *(__half2*)(dstb + base + sig16(j + 2)) = __floats2half2_rn(v.z, v.w);
}

// ---------------------------------------------------------------------------
// fp16 warp-MMA GEMM (k-dim sigma-permuted operands -> all LDS.64 fragments)
// CTA 128x128, 8 warps (64x32), BK=64 halves, 2-stage cp.async.
// MODE 0: half out, [B,H,S,HD], hd sigma-permuted (Q/K)
// MODE 1: half out, [B,H,HD,S], s sigma-permuted (V)
// MODE 2: float out, [M,N] plain (output projection)
// ---------------------------------------------------------------------------
#define GSTR 80              // halves per row (64 + 16 pad) = 40 words
#define GSTAGE_H (128*GSTR)

template <int MODE>
__device__ __forceinline__
void gemm_body(__half* smemh,
               const __half* __restrict__ A, const __half* __restrict__ W,
               const float* __restrict__ bias, void* __restrict__ Cv, float oscale)
{
    __half* As = smemh;
    __half* Ws = smemh + 2*GSTAGE_H;
    const uint32_t As_u = smem_u32(As);
    const uint32_t Ws_u = smem_u32(Ws);

    const int tid  = threadIdx.x;
    const int lane = tid & 31, wid = tid >> 5;
    const int q = lane & 3, g = lane >> 2;
    const int mbase = (wid >> 2) * 64;
    const int nbase = (wid & 3) * 32;
    const int rowBase = blockIdx.y * 128;
    const int colBase = blockIdx.x * 128;

    int lrow[4], lcol[4];
    #pragma unroll
    for (int i = 0; i < 4; i++) {
        int c = tid + i*256;
        lrow[i] = c >> 3;
        lcol[i] = (c & 7) * 8;
    }

    float d[4][4][4];
    #pragma unroll
    for (int mt = 0; mt < 4; mt++)
        #pragma unroll
        for (int nt = 0; nt < 4; nt++)
            #pragma unroll
            for (int e = 0; e < 4; e++) d[mt][nt][e] = 0.f;

    auto issue = [&](int kt) {
        const int slot = kt & 1;
        const uint32_t adst = As_u + (uint32_t)(slot * GSTAGE_H) * 2u;
        const uint32_t wdst = Ws_u + (uint32_t)(slot * GSTAGE_H) * 2u;
        #pragma unroll
        for (int i = 0; i < 4; i++) {
            const uint32_t off = (uint32_t)(lrow[i]*GSTR + lcol[i]) * 2u;
            CP_ASYNC16(adst + off, A + (size_t)(rowBase + lrow[i])*DD + kt*64 + lcol[i]);
            CP_ASYNC16(wdst + off, W + (size_t)(colBase + lrow[i])*DD + kt*64 + lcol[i]);
        }
        CP_COMMIT();
    };

    issue(0);

    for (int kt = 0; kt < 16; kt++) {
        CP_WAIT0();
        __syncthreads();
        if (kt + 1 < 16) issue(kt + 1);

        const __half* A_s = As + (kt & 1) * GSTAGE_H;
        const __half* W_s = Ws + (kt & 1) * GSTAGE_H;
        #pragma unroll
        for (int ks = 0; ks < 4; ks++) {
            uint32_t af[4][4], bf[4][2];
            #pragma unroll
            for (int mt = 0; mt < 4; mt++) {
                const int r0 = mbase + mt*16 + g;
                uint2 a01 = *(const uint2*)(A_s + r0*GSTR     + ks*16 + 4*q);
                uint2 a23 = *(const uint2*)(A_s + (r0+8)*GSTR + ks*16 + 4*q);
                af[mt][0] = a01.x; af[mt][1] = a23.x;
                af[mt][2] = a01.y; af[mt][3] = a23.y;
            }
            #pragma unroll
            for (int nt = 0; nt < 4; nt++) {
                const int n0 = nbase + nt*8 + g;
                uint2 bb = *(const uint2*)(W_s + n0*GSTR + ks*16 + 4*q);
                bf[nt][0] = bb.x; bf[nt][1] = bb.y;
            }
            #pragma unroll
            for (int mt = 0; mt < 4; mt++)
                #pragma unroll
                for (int nt = 0; nt < 4; nt++)
                    mma_f16(d[mt][nt], af[mt], bf[nt]);
        }
    }

    #pragma unroll
    for (int nt = 0; nt < 4; nt++) {
        const int n0 = colBase + nbase + nt*8 + 2*q;
        const float b0 = bias[n0], b1 = bias[n0 + 1];
        #pragma unroll
        for (int mt = 0; mt < 4; mt++) {
            const int m0 = rowBase + mbase + mt*16 + g;
            #pragma unroll
            for (int half = 0; half < 2; half++) {
                const int m = m0 + half*8;
                const float f0 = (d[mt][nt][half*2 + 0] + b0) * oscale;
                const float f1 = (d[mt][nt][half*2 + 1] + b1) * oscale;
                if (MODE == 2) {
                    float2 o; o.x = f0; o.y = f1;
                    *(float2*)((float*)Cv + (size_t)m*DD + n0) = o;
                } else {
                    const int b  = m >> 11;
                    const int s  = m & (SS - 1);
                    const int h  = n0 >> 6;
                    const int hd = n0 & 63;
                    if (MODE == 0) {
                        // hd sigma-permuted (attention d-dim = MMA k-dim)
                        const int hds = (hd & ~15) | sig16(hd & 15);
                        __half2 o = __floats2half2_rn(f0, f1);
                        *(__half2*)((__half*)Cv + (((size_t)(b*HH + h)*SS + s)*HD + hds)) = o;
                    } else {   // MODE 1: V transposed, s sigma-permuted (PV k-dim)
                        const int sp = (s & ~15) | sig16(s & 15);
                        __half* Cp = (__half*)Cv + ((size_t)(b*HH + h)*HD + hd)*SS + sp;
                        Cp[0]  = __float2half_rn(f0);
                        Cp[SS] = __float2half_rn(f1);
                    }
                }
            }
        }
    }
}

__global__ __launch_bounds__(256, 2)
void gemm_qkv(const __half* __restrict__ A, const __half* __restrict__ Wr,
              const float* __restrict__ b0, const float* __restrict__ b1,
              const float* __restrict__ b2,
              __half* __restrict__ C0, __half* __restrict__ C1, __half* __restrict__ C2)
{
    extern __shared__ __half smemh[];
    const int z = blockIdx.z;
    const __half* W = Wr + (size_t)z * DD * DD;
    if (z == 2) {
        gemm_body<1>(smemh, A, W, b2, C2, 1.0f);
    } else if (z == 0) {
        gemm_body<0>(smemh, A, W, b0, C0, QSCALE);
    } else {
        gemm_body<0>(smemh, A, W, b1, C1, 1.0f);
    }
}

__global__ __launch_bounds__(256, 2)
void gemm_out(const __half* __restrict__ A, const __half* __restrict__ W,
              const float* __restrict__ bias, float* __restrict__ C)
{
    extern __shared__ __half smemh[];
    gemm_body<2>(smemh, A, W, bias, C, 1.0f);
}

// ---------------------------------------------------------------------------
// fp16 warp-MMA flash-attention (all fragment loads LDS.64 via permuted dims)
// ---------------------------------------------------------------------------
#define ASTR 80
#define AKBUF (64*ASTR)

__global__ __launch_bounds__(256, 2)
void attn_mma(const __half* __restrict__ Q, const __half* __restrict__ K,
              const __half* __restrict__ Vt, __half* __restrict__ ctx)
{
    extern __shared__ __half sh[];
    __half* Qs = sh;                   // [128][80]
    __half* Ks = sh + 128*ASTR;        // [2][64][80]
    __half* Vs = Ks + 2*AKBUF;         // [2][64][80] (d-major, keys permuted)
    const uint32_t Qs_u = smem_u32(Qs);
    const uint32_t Ks_u = smem_u32(Ks);
    const uint32_t Vs_u = smem_u32(Vs);

    const int tid  = threadIdx.x;
    const int lane = tid & 31, wid = tid >> 5;
    const int q = lane & 3, g = lane >> 2;
    const int bh = blockIdx.y, qt = blockIdx.x;

    const __half* Qb = Q  + (size_t)bh*SS*HD + (size_t)qt*128*HD;
    const __half* Kb = K  + (size_t)bh*SS*HD;
    const __half* Vb = Vt + (size_t)bh*HD*SS;

    auto issue_kv = [&](int kt) {
        const int buf = kt & 1;
        #pragma unroll
        for (int i = 0; i < 2; i++) {
            const int c = tid + i*256;
            const int r = c >> 3, c8 = (c & 7) * 8;
            const uint32_t off = (uint32_t)(buf*AKBUF + r*ASTR + c8) * 2u;
            CP_ASYNC16(Ks_u + off, Kb + (size_t)(kt*64 + r)*HD + c8);
            CP_ASYNC16(Vs_u + off, Vb + (size_t)r*SS + kt*64 + c8);
        }
        CP_COMMIT();
    };

    #pragma unroll
    for (int i = 0; i < 4; i++) {
        const int c = tid + i*256;
        const int r = c >> 3, c8 = (c & 7) * 8;
        CP_ASYNC16(Qs_u + (uint32_t)(r*ASTR + c8)*2u, Qb + r*HD + c8);
    }
    issue_kv(0);

    const int r0 = wid*16 + g;

    float m0 = -1e30f, m1 = -1e30f, l0 = 0.f, l1 = 0.f;
    float o[8][4];
    #pragma unroll
    for (int nt = 0; nt < 8; nt++)
        #pragma unroll
        for (int e = 0; e < 4; e++) o[nt][e] = 0.f;

    const uint32_t bones = 0x3C003C00u;
    const uint32_t bo2[2] = { bones, bones };

    for (int kt = 0; kt < SS/64; kt++) {
        CP_WAIT0();
        __syncthreads();
        if (kt + 1 < SS/64) issue_kv(kt + 1);

        const __half* Kc = Ks + (kt & 1) * AKBUF;
        const __half* Vc = Vs + (kt & 1) * AKBUF;

        // --- QK^T (log2 units) ---
        float s[8][4];
        #pragma unroll
        for (int nt = 0; nt < 8; nt++)
            #pragma unroll
            for (int e = 0; e < 4; e++) s[nt][e] = 0.f;

        #pragma unroll
        for (int ks = 0; ks < 4; ks++) {
            uint32_t a[4];
            uint2 qa01 = *(const uint2*)(Qs + r0*ASTR     + ks*16 + 4*q);
            uint2 qa23 = *(const uint2*)(Qs + (r0+8)*ASTR + ks*16 + 4*q);
            a[0] = qa01.x; a[1] = qa23.x; a[2] = qa01.y; a[3] = qa23.y;
            #pragma unroll
            for (int p = 0; p < 8; p++) {
                uint2 bb = *(const uint2*)(Kc + (p*8 + g)*ASTR + ks*16 + 4*q);
                uint32_t b[2] = { bb.x, bb.y };
                mma_f16(s[p], a, b);
            }
        }

        // --- online softmax (log2 domain) ---
        float mx0 = -1e30f, mx1 = -1e30f;
        #pragma unroll
        for (int nt = 0; nt < 8; nt++) {
            mx0 = fmaxf(mx0, fmaxf(s[nt][0], s[nt][1]));
            mx1 = fmaxf(mx1, fmaxf(s[nt][2], s[nt][3]));
        }
        mx0 = fmaxf(mx0, __shfl_xor_sync(0xffffffffu, mx0, 1));
        mx0 = fmaxf(mx0, __shfl_xor_sync(0xffffffffu, mx0, 2));
        mx1 = fmaxf(mx1, __shfl_xor_sync(0xffffffffu, mx1, 1));
        mx1 = fmaxf(mx1, __shfl_xor_sync(0xffffffffu, mx1, 2));

        const float mn0 = fmaxf(m0, mx0), mn1 = fmaxf(m1, mx1);
        const float al0 = exp2f(m0 - mn0), al1 = exp2f(m1 - mn1);
        m0 = mn0; m1 = mn1;

        #pragma unroll
        for (int nt = 0; nt < 8; nt++) {
            o[nt][0] *= al0; o[nt][1] *= al0;
            o[nt][2] *= al1; o[nt][3] *= al1;
        }

        // --- P = exp2(s - mn); PV + ones-MMA row sums ---
        float lc[4] = {0.f, 0.f, 0.f, 0.f};
        #pragma unroll
        for (int ks = 0; ks < 4; ks++) {
            uint32_t a[4];
            a[0] = h2_bits(h2exp2(__floats2half2_rn(s[2*ks][0]   - mn0, s[2*ks][1]   - mn0)));
            a[1] = h2_bits(h2exp2(__floats2half2_rn(s[2*ks][2]   - mn1, s[2*ks][3]   - mn1)));
            a[2] = h2_bits(h2exp2(__floats2half2_rn(s[2*ks+1][0] - mn0, s[2*ks+1][1] - mn0)));
            a[3] = h2_bits(h2exp2(__floats2half2_rn(s[2*ks+1][2] - mn1, s[2*ks+1][3] - mn1)));
            mma_f16(lc, a, bo2);
            #pragma unroll
            for (int nt = 0; nt < 8; nt++) {
                uint2 bb = *(const uint2*)(Vc + (nt*8 + g)*ASTR + ks*16 + 4*q);
                uint32_t b[2] = { bb.x, bb.y };
                mma_f16(o[nt], a, b);
            }
        }
        l0 = l0 * al0 + lc[0];
        l1 = l1 * al1 + lc[2];
    }

    // normalize + write ctx, D columns sigma-permuted (gemm_out k-dim)
    const float inv0 = 1.f / l0, inv1 = 1.f / l1;
    const int b = bh >> 4, h = bh & 15;
    const int row0 = qt*128 + r0;
    __half* dst0 = ctx + ((size_t)(b*SS + row0))*DD + h*64;
    __half* dst1 = ctx + ((size_t)(b*SS + row0 + 8))*DD + h*64;
    #pragma unroll
    for (int nt = 0; nt < 8; nt++) {
        const int c64 = nt*8 + 2*q;
        const int cs  = (c64 & ~15) | sig16(c64 & 15);
        *(__half2*)(dst0 + cs) = __floats2half2_rn(o[nt][0]*inv0, o[nt][1]*inv0);
        *(__half2*)(dst1 + cs) = __floats2half2_rn(o[nt][2]*inv1, o[nt][3]*inv1);
    }
}

// ---------------------------------------------------------------------------
extern "C" void kernel_launch(void* const* d_in, const int* in_sizes, int n_in,
                              void* d_out, int out_size)
{
    const float* x  = (const float*)d_in[0];
    const float* Wq = (const float*)d_in[1];
    const float* bq = (const float*)d_in[2];
    const float* Wk = (const float*)d_in[3];
    const float* bk = (const float*)d_in[4];
    const float* Wv = (const float*)d_in[5];
    const float* bv = (const float*)d_in[6];
    const float* Wo = (const float*)d_in[7];
    const float* bo = (const float*)d_in[8];

    __half *q, *k, *v, *ctx, *xr, *wr;
    cudaGetSymbolAddress((void**)&q,   g_q);
    cudaGetSymbolAddress((void**)&k,   g_k);
    cudaGetSymbolAddress((void**)&v,   g_v);
    cudaGetSymbolAddress((void**)&ctx, g_ctx);
    cudaGetSymbolAddress((void**)&xr,  g_xr);
    cudaGetSymbolAddress((void**)&wr,  g_wr);

    const int smem_gemm = 2 * 2 * GSTAGE_H * (int)sizeof(__half);        // 81920
    const int smem_attn = (128*ASTR + 4*AKBUF) * (int)sizeof(__half);    // 61440
    cudaFuncSetAttribute(gemm_qkv,
                         cudaFuncAttributeMaxDynamicSharedMemorySize, smem_gemm);
    cudaFuncSetAttribute(gemm_out,
                         cudaFuncAttributeMaxDynamicSharedMemorySize, smem_gemm);
    cudaFuncSetAttribute(attn_mma,
                         cudaFuncAttributeMaxDynamicSharedMemorySize, smem_attn);

    round_prep<<<(XR_F4 + 4*WR_F4) / 256, 256>>>(x, Wq, Wk, Wv, Wo, xr, wr);

    dim3 qkvgrid(DD/128, MM/128, 3);
    gemm_qkv<<<qkvgrid, 256, smem_gemm>>>(xr, wr, bq, bk, bv, q, k, v);

    dim3 agrid(SS/128, BB*HH);
    attn_mma<<<agrid, 256, smem_attn>>>(q, k, v, ctx);

    dim3 ogrid(DD/128, MM/128);
    gemm_out<<<ogrid, 256, smem_gemm>>>(ctx, wr + (size_t)3*DD*DD, bo, (float*)d_out);
}